// round 14
// baseline (speedup 1.0000x reference)
#include <cuda_runtime.h>
#include <math.h>

#define B_ 2
#define T_ 4096
#define C_ 192
#define NTOT (B_*T_*C_)

// ---------------- scratch ----------------
__device__ float g_Wf[384*576];      // tf32-pre-rounded fused [k|v|r] weights
__device__ float g_Wo[192*192];      // tf32-pre-rounded output weights
__device__ float g_Wp[192*32];       // exact fp32 conv-tap weights
__device__ float g_A[B_*T_*384];     // tf32-pre-rounded [x | qshift(x)]
__device__ float g_P[B_*T_*32];
__device__ float g_peakT[NTOT];      // peak, (B,C,T) layout
__device__ float g_kT[NTOT];
__device__ float g_vT[NTOT];
__device__ float g_yT[NTOT];
__device__ float g_sr[NTOT];

__constant__ float c_prfx[16] = {-2,-2,-2,-2, -2,-1,0,1,  2,2,2,2,  -1,0,1,2};
__constant__ float c_prfy[16] = {-2,-1,0,1,   2,2,2,2,  -1,0,1,2,  -2,-2,-2,-2};

__device__ __forceinline__ unsigned f2tf32(float x) {
    unsigned r;
    asm("cvt.rna.tf32.f32 %0, %1;" : "=r"(r) : "f"(x));
    return r;
}

__device__ __forceinline__ void mma8(float* d, unsigned a0, unsigned a1, unsigned a2, unsigned a3,
                                     unsigned b0, unsigned b1) {
    asm volatile(
        "mma.sync.aligned.m16n8k8.row.col.f32.tf32.tf32.f32 "
        "{%0,%1,%2,%3}, {%4,%5,%6,%7}, {%8,%9}, {%0,%1,%2,%3};\n"
        : "+f"(d[0]), "+f"(d[1]), "+f"(d[2]), "+f"(d[3])
        : "r"(a0), "r"(a1), "r"(a2), "r"(a3), "r"(b0), "r"(b1));
}

// ---------------- prep_w: weights only ----------------
__global__ __launch_bounds__(384) void prepw_kernel(const float* __restrict__ mk,
                                                    const float* __restrict__ mv,
                                                    const float* __restrict__ mr,
                                                    const float* __restrict__ Wk,
                                                    const float* __restrict__ Wv,
                                                    const float* __restrict__ Wr,
                                                    const float* __restrict__ Wo,
                                                    const float* __restrict__ cvw,
                                                    const float* __restrict__ chw) {
    int i = blockIdx.x * 384 + threadIdx.x;
    if (i < 384*576) {
        int row = i / 576, n = i % 576;
        int c = row % 192;
        bool second = row >= 192;
        const float* W; float m; int nn;
        if (n < 192)      { W = Wk; m = mk[c]; nn = n; }
        else if (n < 384) { W = Wv; m = mv[c]; nn = n - 192; }
        else              { W = Wr; m = mr[c]; nn = n - 384; }
        float v = (second ? (1.f - m) : m) * W[c*192 + nn];
        g_Wf[i] = __uint_as_float(f2tf32(v));
        return;
    }
    int j = i - 384*576;
    if (j < 192*32) {
        int c = j / 32, n = j % 32;
        float v = 0.f;
        if (n < 14)      v = cvw[(n/7)*C_*7 + c*7 + (n%7)];
        else if (n < 28) { int n2 = n - 14; v = chw[(n2/7)*C_*7 + c*7 + (n2%7)]; }
        g_Wp[j] = v;
        return;
    }
    int jj = j - 192*32;
    if (jj < 192*192)
        g_Wo[jj] = __uint_as_float(f2tf32(Wo[jj]));
}

// ---------------- prep_A (vectorized): g_A = tf32([x | qshift(x)]) ----------------
__global__ __launch_bounds__(384) void prepa_kernel(const float* __restrict__ x) {
    const float4* x4 = (const float4*)x;
    float4* A4 = (float4*)g_A;
    int tb = blockIdx.x * 16;                 // 512 blocks x 16 tokens
    int j0 = threadIdx.x / 96;                // 0..3
    int f4 = threadIdx.x % 96;                // float4 index within 384-ch row
    bool shifted = f4 >= 48;
    int c4f = shifted ? (f4 - 48) : f4;       // 0..47 float4 within 192 ch
    int g = c4f / 12;                         // 48-ch group
#pragma unroll
    for (int rep = 0; rep < 4; rep++) {
        int gt = tb + j0 + rep*4;
        float4 v;
        if (!shifted) {
            v = x4[(size_t)gt*48 + c4f];
        } else {
            int tt = gt & 4095;
            int hh = tt >> 6, ww = tt & 63;
            int src; bool ok;
            if (g == 0)      { ok = (ww >= 1);  src = gt - 1; }
            else if (g == 1) { ok = (ww <= 62); src = gt + 1; }
            else if (g == 2) { ok = (hh >= 1);  src = gt - 64; }
            else             { ok = (hh <= 62); src = gt + 64; }
            v = ok ? x4[(size_t)src*48 + c4f] : make_float4(0.f, 0.f, 0.f, 0.f);
        }
        float4 o;
        o.x = __uint_as_float(f2tf32(v.x));
        o.y = __uint_as_float(f2tf32(v.y));
        o.z = __uint_as_float(f2tf32(v.z));
        o.w = __uint_as_float(f2tf32(v.w));
        A4[(size_t)gt*96 + f4] = o;
    }
}

// ---------------- convP: g_P = x @ Wp (fp32 exact) ----------------
__global__ __launch_bounds__(256) void convP_kernel(const float* __restrict__ x) {
    __shared__ float xs[8][193];
    int tid = threadIdx.x;
    int tok0 = blockIdx.x * 8;
    for (int i = tid; i < 8*192; i += 256) {
        int r = i / 192, c = i % 192;
        xs[r][c] = x[(size_t)(tok0 + r)*C_ + c];
    }
    __syncthreads();
    int r = tid >> 5, n = tid & 31;
    if (n < 28) {
        float acc = 0.f;
#pragma unroll 8
        for (int c = 0; c < 192; c++)
            acc = fmaf(xs[r][c], g_Wp[c*32 + n], acc);
        g_P[(size_t)(tok0 + r)*32 + n] = acc;
    }
}

// ---------------- adaptive peak -> transposed output (B,C,T) ----------------
__global__ __launch_bounds__(384) void peak_kernel(const float* __restrict__ x,
                                                   const float* __restrict__ cvb,
                                                   const float* __restrict__ bns_v,
                                                   const float* __restrict__ bnb_v,
                                                   const float* __restrict__ chb,
                                                   const float* __restrict__ bns_h,
                                                   const float* __restrict__ bnb_h) {
    int bi = blockIdx.x;                  // 512 blocks
    int b = bi >> 8;
    int tb = (bi & 255) * 16;
    int hh = tb >> 6, wwb = tb & 63;
    __shared__ float gbv[16][4];
    __shared__ int   s_lt[16][16], s_rb[16][16];
    __shared__ float s_wlt[16][16], s_wrb[16][16];
    __shared__ float st[192*17];          // [channel][token] stage, pad 17
    int tid = threadIdx.x;

    if (tid < 64) {
        int j = tid >> 2, dir = tid & 3;
        int ww = wwb + j;
        const float* Pb = g_P + (size_t)b * T_ * 32;
        float s = 0.f;
        if (dir < 2) {
#pragma unroll
            for (int r = 0; r < 7; r++) {
                int hy = hh + r - 3;
                if (hy >= 0 && hy < 64) s += Pb[(size_t)(hy*64 + ww)*32 + dir*7 + r];
            }
        } else {
#pragma unroll
            for (int r = 0; r < 7; r++) {
                int wy = ww + r - 3;
                if (wy >= 0 && wy < 64) s += Pb[(size_t)(hh*64 + wy)*32 + (dir-2)*7 + 14 + r];
            }
        }
        const float inv = rsqrtf(1.f + 1e-5f);
        float bias, scale, shift;
        if (dir == 0)      { bias = cvb[0]; scale = bns_v[0]; shift = bnb_v[0]; }
        else if (dir == 1) { bias = cvb[1]; scale = bns_v[1]; shift = bnb_v[1]; }
        else if (dir == 2) { bias = chb[0]; scale = bns_h[0]; shift = bnb_h[0]; }
        else               { bias = chb[1]; scale = bns_h[1]; shift = bnb_h[1]; }
        float val = (s + bias) * (scale * inv) + shift;
        gbv[j][dir] = 2.f / (1.f + expf(-val));
    }
    __syncthreads();

    if (tid < 256) {
        int j = tid >> 4, o = tid & 15;
        int ww = wwb + j;
        int blk = o >> 2;
        float mx = 0.f, my = 0.f;
        if (blk == 0)      mx = -gbv[j][0];
        else if (blk == 1) my =  gbv[j][3];
        else if (blk == 2) mx =  gbv[j][1];
        else               my = -gbv[j][2];
        float px = (float)(hh + 2) + c_prfx[o] + mx;
        float py = (float)(ww + 2) + c_prfy[o] + my;
        float flx = floorf(px), fly = floorf(py);
        float qltx = fminf(fmaxf(flx,     0.f), 67.f);
        float qlty = fminf(fmaxf(fly,     0.f), 67.f);
        float qrbx = fminf(fmaxf(flx+1.f, 0.f), 67.f);
        float qrby = fminf(fmaxf(fly+1.f, 0.f), 67.f);
        float pxc  = fminf(fmaxf(px,      0.f), 67.f);
        float pyc  = fminf(fmaxf(py,      0.f), 67.f);
        float glt = (1.f + (qltx - pxc)) * (1.f + (qlty - pyc));
        float grb = (1.f - (qrbx - pxc)) * (1.f - (qrby - pyc));
        int rlt = min(max((int)qltx - 2, 0), 63);
        int clt = min(max((int)qlty - 2, 0), 63);
        int rrb = min(max((int)qrbx - 2, 0), 63);
        int crb = min(max((int)qrby - 2, 0), 63);
        s_lt[j][o] = rlt*64 + clt;  s_rb[j][o] = rrb*64 + crb;
        s_wlt[j][o] = glt;          s_wrb[j][o] = grb;
    }
    __syncthreads();

    const float* xb = x + (size_t)b * T_ * C_;
    int slot = tid / 48;
    int c4 = (tid % 48) * 4;
#pragma unroll
    for (int rep = 0; rep < 2; rep++) {
        int j = slot + rep*8;
        float a0 = 0.f, a1 = 0.f, a2 = 0.f, a3 = 0.f;
#pragma unroll
        for (int o = 0; o < 16; o++) {
            float4 a = *(const float4*)&xb[(size_t)s_lt[j][o]*C_ + c4];
            float4 bv = *(const float4*)&xb[(size_t)s_rb[j][o]*C_ + c4];
            float wl = s_wlt[j][o], wr = s_wrb[j][o];
            a0 += wl*a.x + wr*bv.x;
            a1 += wl*a.y + wr*bv.y;
            a2 += wl*a.z + wr*bv.z;
            a3 += wl*a.w + wr*bv.w;
        }
        size_t idx = ((size_t)b*T_ + tb + j)*C_ + c4;
        float4 xc = *(const float4*)&x[idx];
        st[(c4+0)*17 + j] = xc.x - a0*(1.f/16.f);
        st[(c4+1)*17 + j] = xc.y - a1*(1.f/16.f);
        st[(c4+2)*17 + j] = xc.z - a2*(1.f/16.f);
        st[(c4+3)*17 + j] = xc.w - a3*(1.f/16.f);
    }
    __syncthreads();

#pragma unroll
    for (int q = 0; q < 2; q++) {
        int f = tid + q*384;
        int cr = f >> 2;
        int t4 = (f & 3) * 4;
        float4 v;
        v.x = st[cr*17 + t4 + 0];
        v.y = st[cr*17 + t4 + 1];
        v.z = st[cr*17 + t4 + 2];
        v.w = st[cr*17 + t4 + 3];
        *(float4*)&g_peakT[((size_t)(b*C_ + cr))*T_ + tb + t4] = v;
    }
}

// ---------------- fused front GEMM: block 128x96, 8 warps, warp 32x48 ----------------
#define AS1 36
#define BS1 104
#define A_BUF (128*AS1)
#define B_BUF (32*BS1)

__global__ __launch_bounds__(256) void gemm1_kernel() {
    extern __shared__ float smem[];
    float* AsBuf = smem;
    float* BsBuf = smem + 2*A_BUF;

    int tid = threadIdx.x;
    int warp = tid >> 5, lane = tid & 31;
    int bm = blockIdx.x * 128;
    int bny = blockIdx.y;                // 0..5
    int bn = bny * 96;
    int cls = bny >> 1;                  // 0:k 1:v 2:r
    int nloc = (bny & 1) * 96;
    int wm = (warp >> 1) * 32;
    int wn = (warp & 1) * 48;
    int gid = lane >> 2, tig = lane & 3;

    const float* Abase = g_A + (size_t)bm * 384;
    float acc[2][6][4] = {};

    float4 pa[4], pb[3];
#pragma unroll
    for (int q = 0; q < 4; q++) {
        int f = tid + q*256;
        pa[q] = *(const float4*)&Abase[(size_t)(f >> 3)*384 + (f & 7)*4];
    }
#pragma unroll
    for (int q = 0; q < 3; q++) {
        int f = tid + q*256;
        pb[q] = *(const float4*)&g_Wf[(size_t)(f/24)*576 + bn + (f%24)*4];
    }
#pragma unroll
    for (int q = 0; q < 4; q++) {
        int f = tid + q*256;
        *(float4*)&AsBuf[(f >> 3)*AS1 + (f & 7)*4] = pa[q];
    }
#pragma unroll
    for (int q = 0; q < 3; q++) {
        int f = tid + q*256;
        *(float4*)&BsBuf[(f/24)*BS1 + (f%24)*4] = pb[q];
    }
    __syncthreads();

    for (int kc = 0; kc < 12; kc++) {
        int cur = kc & 1;
        if (kc < 11) {
            int k0 = (kc + 1) * 32;
#pragma unroll
            for (int q = 0; q < 4; q++) {
                int f = tid + q*256;
                pa[q] = *(const float4*)&Abase[(size_t)(f >> 3)*384 + k0 + (f & 7)*4];
            }
#pragma unroll
            for (int q = 0; q < 3; q++) {
                int f = tid + q*256;
                pb[q] = *(const float4*)&g_Wf[(size_t)(k0 + f/24)*576 + bn + (f%24)*4];
            }
        }
        const float* as = AsBuf + cur*A_BUF;
        const float* bs = BsBuf + cur*B_BUF;
#pragma unroll
        for (int ks = 0; ks < 4; ks++) {
            int kk0 = ks * 8;
            unsigned afr[2][4], bfr[6][2];
#pragma unroll
            for (int mi = 0; mi < 2; mi++) {
                int rbase = (wm + mi*16 + gid) * AS1;
                afr[mi][0] = __float_as_uint(as[rbase + kk0 + tig]);
                afr[mi][1] = __float_as_uint(as[rbase + 8*AS1 + kk0 + tig]);
                afr[mi][2] = __float_as_uint(as[rbase + kk0 + tig + 4]);
                afr[mi][3] = __float_as_uint(as[rbase + 8*AS1 + kk0 + tig + 4]);
            }
#pragma unroll
            for (int ni = 0; ni < 6; ni++) {
                int col = wn + ni*8 + gid;
                bfr[ni][0] = __float_as_uint(bs[(kk0 + tig)*BS1 + col]);
                bfr[ni][1] = __float_as_uint(bs[(kk0 + tig + 4)*BS1 + col]);
            }
#pragma unroll
            for (int mi = 0; mi < 2; mi++)
#pragma unroll
                for (int ni = 0; ni < 6; ni++)
                    mma8(acc[mi][ni], afr[mi][0], afr[mi][1], afr[mi][2], afr[mi][3],
                         bfr[ni][0], bfr[ni][1]);
        }
        if (kc < 11) {
            __syncthreads();
            int nxt = cur ^ 1;
#pragma unroll
            for (int q = 0; q < 4; q++) {
                int f = tid + q*256;
                *(float4*)&AsBuf[nxt*A_BUF + (f >> 3)*AS1 + (f & 7)*4] = pa[q];
            }
#pragma unroll
            for (int q = 0; q < 3; q++) {
                int f = tid + q*256;
                *(float4*)&BsBuf[nxt*B_BUF + (f/24)*BS1 + (f%24)*4] = pb[q];
            }
            __syncthreads();
        }
    }

    if (cls == 2) {
#pragma unroll
        for (int mi = 0; mi < 2; mi++) {
            int r0 = bm + wm + mi*16 + gid;
#pragma unroll
            for (int ni = 0; ni < 6; ni++) {
                int c0 = nloc + wn + ni*8 + tig*2;
                float v0 = 1.f/(1.f+expf(-acc[mi][ni][0]));
                float v1 = 1.f/(1.f+expf(-acc[mi][ni][1]));
                float v2 = 1.f/(1.f+expf(-acc[mi][ni][2]));
                float v3 = 1.f/(1.f+expf(-acc[mi][ni][3]));
                *(float2*)&g_sr[(size_t)r0*C_ + c0]     = make_float2(v0, v1);
                *(float2*)&g_sr[(size_t)(r0+8)*C_ + c0] = make_float2(v2, v3);
            }
        }
        return;
    }

    // k and v: transpose stage st[channel][token], stride 132
    __syncthreads();
    float* st = smem;
#pragma unroll
    for (int mi = 0; mi < 2; mi++) {
        int r = wm + mi*16 + gid;
#pragma unroll
        for (int ni = 0; ni < 6; ni++) {
            int cc = wn + ni*8 + tig*2;
            st[cc*132 + r]         = acc[mi][ni][0];
            st[(cc+1)*132 + r]     = acc[mi][ni][1];
            st[cc*132 + r + 8]     = acc[mi][ni][2];
            st[(cc+1)*132 + r + 8] = acc[mi][ni][3];
        }
    }
    __syncthreads();
    float* dst = (cls == 0) ? g_kT : g_vT;
    int bb = bm >> 12, trow = bm & 4095;
#pragma unroll
    for (int q = 0; q < 12; q++) {
        int f = q*256 + tid;
        int cr = f >> 5;
        int t4 = (f & 31) * 4;
        float4 v = *(const float4*)&st[cr*132 + t4];
        *(float4*)&dst[((size_t)(bb*C_ + nloc + cr))*T_ + trow + t4] = v;
    }
}

// ---------------- bidirectional WKV scan (v = vT + peakT on load) ----------------
struct Agg { float a, b, dl; };
__device__ __forceinline__ Agg combine(Agg p, Agg s) {
    Agg r;
    r.a  = fmaf(s.dl, p.a, s.a);
    r.b  = fmaf(s.dl, p.b, s.b);
    r.dl = p.dl * s.dl;
    return r;
}
__device__ __forceinline__ Agg shfl_up_agg(Agg v, int off) {
    Agg r;
    r.a  = __shfl_up_sync(0xffffffffu, v.a,  off);
    r.b  = __shfl_up_sync(0xffffffffu, v.b,  off);
    r.dl = __shfl_up_sync(0xffffffffu, v.dl, off);
    return r;
}
__device__ __forceinline__ Agg shfl_dn_agg(Agg v, int off) {
    Agg r;
    r.a  = __shfl_down_sync(0xffffffffu, v.a,  off);
    r.b  = __shfl_down_sync(0xffffffffu, v.b,  off);
    r.dl = __shfl_down_sync(0xffffffffu, v.dl, off);
    return r;
}

__global__ __launch_bounds__(256) void wkv_kernel(const float* __restrict__ sd,
                                                  const float* __restrict__ sf) {
    __shared__ float eks[4352];
    __shared__ float vvs[4352];
    __shared__ Agg warpAgg[8];
    __shared__ Agg warpPre[8];
    int bc = blockIdx.x;
    int c = bc % C_;
    float w  = sd[c] * (1.0f / T_);
    float u  = sf[c] * (1.0f / T_);
    float d  = expf(-w);
    float eu = expf(u);
    float d2 = d*d, d4 = d2*d2, d8 = d4*d4, d16 = d8*d8;
    int tid = threadIdx.x;
    int lane = tid & 31, wid = tid >> 5;
    const float4* kp4 = (const float4*)(g_kT + (size_t)bc * T_);
    const float4* vp4 = (const float4*)(g_vT + (size_t)bc * T_);
    const float4* pk4 = (const float4*)(g_peakT + (size_t)bc * T_);

#pragma unroll
    for (int q = 0; q < 4; q++) {
        int idx = tid + q*256;
        float4 kv = kp4[idx];
        float4 v4 = vp4[idx];
        float4 p4 = pk4[idx];
        v4.x += p4.x; v4.y += p4.y; v4.z += p4.z; v4.w += p4.w;
        int t = idx * 4;
        int base = t + (t >> 4);
        eks[base+0] = expf(kv.x); eks[base+1] = expf(kv.y);
        eks[base+2] = expf(kv.z); eks[base+3] = expf(kv.w);
        vvs[base+0] = v4.x; vvs[base+1] = v4.y;
        vvs[base+2] = v4.z; vvs[base+3] = v4.w;
    }
    __syncthreads();

    float ek[16], vv[16];
    int rb = 17 * tid;
#pragma unroll
    for (int i = 0; i < 16; i++) { ek[i] = eks[rb + i]; vv[i] = vvs[rb + i]; }

    Agg ag; ag.a = 0.f; ag.b = 0.f; ag.dl = d16;
#pragma unroll
    for (int i = 0; i < 16; i++) {
        ag.a = fmaf(d, ag.a, ek[i]);
        ag.b = fmaf(d, ag.b, ek[i]*vv[i]);
    }
    Agg inc = ag;
#pragma unroll
    for (int off = 1; off < 32; off <<= 1) {
        Agg o = shfl_up_agg(inc, off);
        if (lane >= off) inc = combine(o, inc);
    }
    if (lane == 31) warpAgg[wid] = inc;
    __syncthreads();
    if (tid == 0) {
        Agg run; run.a = 0.f; run.b = 0.f; run.dl = 1.f;
        for (int i = 0; i < 8; i++) { warpPre[i] = run; run = combine(run, warpAgg[i]); }
    }
    __syncthreads();
    Agg pl = shfl_up_agg(inc, 1);
    Agg ex = warpPre[wid];
    if (lane > 0) ex = combine(ex, pl);

    float af = ex.a, bf = ex.b;
    float saf[16], sbf[16];
#pragma unroll
    for (int i = 0; i < 16; i++) {
        saf[i] = af; sbf[i] = bf;
        af = fmaf(d, af, ek[i]);
        bf = fmaf(d, bf, ek[i]*vv[i]);
    }
    __syncthreads();

    Agg bg; bg.a = 0.f; bg.b = 0.f; bg.dl = d16;
#pragma unroll
    for (int i = 15; i >= 0; i--) {
        bg.a = fmaf(d, bg.a, ek[i]);
        bg.b = fmaf(d, bg.b, ek[i]*vv[i]);
    }
    Agg binc = bg;
#pragma unroll
    for (int off = 1; off < 32; off <<= 1) {
        Agg o = shfl_dn_agg(binc, off);
        if (lane < 32 - off) binc = combine(o, binc);
    }
    if (lane == 0) warpAgg[wid] = binc;
    __syncthreads();
    if (tid == 0) {
        Agg run; run.a = 0.f; run.b = 0.f; run.dl = 1.f;
        for (int i = 7; i >= 0; i--) { warpPre[i] = run; run = combine(run, warpAgg[i]); }
    }
    __syncthreads();
    Agg bpl = shfl_dn_agg(binc, 1);
    Agg bex = warpPre[wid];
    if (lane < 31) bex = combine(bex, bpl);

    float ab = bex.a, bb = bex.b;
#pragma unroll
    for (int i = 15; i >= 0; i--) {
        float es  = eu * ek[i];
        float num = sbf[i] + bb + es * vv[i];
        float den = saf[i] + ab + es;
        vvs[rb + i] = num / den;
        ab = fmaf(d, ab, ek[i]);
        bb = fmaf(d, bb, ek[i]*vv[i]);
    }
    __syncthreads();

    float4* yp4 = (float4*)(g_yT + (size_t)bc * T_);
#pragma unroll
    for (int q = 0; q < 4; q++) {
        int idx = tid + q*256;
        int t = idx * 4;
        int base = t + (t >> 4);
        yp4[idx] = make_float4(vvs[base+0], vvs[base+1], vvs[base+2], vvs[base+3]);
    }
}

// ---------------- output GEMM (1x tf32): out = (sr .* y) @ Wo ----------------
#define A2_STRIDE 197
#define BS_STRIDE 72

__global__ __launch_bounds__(128) void gemm2_kernel(float* __restrict__ out) {
    __shared__ unsigned As2[32 * A2_STRIDE];
    __shared__ unsigned Bs2[2][32 * BS_STRIDE];

    int tid = threadIdx.x;
    int warp = tid >> 5, lane = tid & 31;
    int gid = lane >> 2, tig = lane & 3;
    int bm = blockIdx.x * 32;
    int bn = blockIdx.y * 64;
    int wm = (warp >> 1) * 16;
    int wn = (warp & 1) * 32;
    int bb = bm >> 12, trow = bm & 4095;

#pragma unroll
    for (int q = 0; q < 12; q++) {
        int f = q*128 + tid;
        int row = f >> 3;
        int t4 = (f & 7) * 4;
        float4 v = *(const float4*)&g_yT[((size_t)(bb*C_ + row))*T_ + trow + t4];
        As2[(t4+0)*A2_STRIDE + row] = __float_as_uint(v.x);
        As2[(t4+1)*A2_STRIDE + row] = __float_as_uint(v.y);
        As2[(t4+2)*A2_STRIDE + row] = __float_as_uint(v.z);
        As2[(t4+3)*A2_STRIDE + row] = __float_as_uint(v.w);
    }
    __syncthreads();
#pragma unroll
    for (int q = 0; q < 12; q++) {
        int f = q*128 + tid;
        int t = f / 48, c4 = (f % 48) * 4;
        float4 s = *(const float4*)&g_sr[((size_t)(bm + t))*C_ + c4];
        unsigned* p = &As2[t*A2_STRIDE + c4];
        p[0] = f2tf32(__uint_as_float(p[0]) * s.x);
        p[1] = f2tf32(__uint_as_float(p[1]) * s.y);
        p[2] = f2tf32(__uint_as_float(p[2]) * s.z);
        p[3] = f2tf32(__uint_as_float(p[3]) * s.w);
    }

    int br = tid >> 4;
    int bc = (tid & 15) * 4;
    float acc[4][4] = {};

    float4 pb[4];
#pragma unroll
    for (int i = 0; i < 4; i++)
        pb[i] = *(const float4*)&g_Wo[(size_t)(br + i*8)*C_ + bn + bc];
#pragma unroll
    for (int i = 0; i < 4; i++)
        *(float4*)&Bs2[0][(br + i*8)*BS_STRIDE + bc] = pb[i];
    __syncthreads();

    for (int kc = 0; kc < 6; kc++) {
        int cur = kc & 1;
        if (kc < 5) {
            int k0 = (kc + 1) * 32;
#pragma unroll
            for (int i = 0; i < 4; i++)
                pb[i] = *(const float4*)&g_Wo[(size_t)(k0 + br + i*8)*C_ + bn + bc];
        }
        const unsigned* bs = Bs2[cur];
        int k0 = kc * 32;
#pragma unroll
        for (int ks = 0; ks < 4; ks++) {
            int kk = k0 + ks*8;
            unsigned a0 = As2[(wm+gid)*A2_STRIDE + kk + tig];
            unsigned a1 = As2[(wm+gid+8)*A2_STRIDE + kk + tig];
            unsigned a2 = As2[(wm+gid)*A2_STRIDE + kk + tig + 4];
            unsigned a3 = As2[(wm+gid+8)*A2_STRIDE + kk + tig + 4];
#pragma unroll
            for (int ni = 0; ni < 4; ni++) {
                int col = wn + ni*8 + gid;
                unsigned b0 = bs[(ks*8 + tig)*BS_STRIDE + col];
                unsigned b1 = bs[(ks*8 + tig + 4)*BS_STRIDE + col];
                mma8(acc[ni], a0, a1, a2, a3, b0, b1);
            }
        }
        if (kc < 5) {
            __syncthreads();
            int nxt = cur ^ 1;
#pragma unroll
            for (int i = 0; i < 4; i++)
                *(float4*)&Bs2[nxt][(br + i*8)*BS_STRIDE + bc] = pb[i];
            __syncthreads();
        }
    }

    int r0 = bm + wm + gid;
#pragma unroll
    for (int ni = 0; ni < 4; ni++) {
        int c0 = bn + wn + ni*8 + tig*2;
        *(float2*)&out[(size_t)r0*C_ + c0]     = make_float2(acc[ni][0], acc[ni][1]);
        *(float2*)&out[(size_t)(r0+8)*C_ + c0] = make_float2(acc[ni][2], acc[ni][3]);
    }
}

// ---------------- launch ----------------
// side:  prepw -> convP -> peak    (evW after prepw, evJoin after peak)
// main:  prepa -> [wait evW] gemm1 -> [wait evJoin] wkv -> gemm2
#define GEMM1_SMEM ((2*A_BUF + 2*B_BUF) * 4)

namespace {
struct SideStream {
    cudaStream_t s1;
    cudaEvent_t evFork, evW, evJoin;
    SideStream() {
        cudaStreamCreateWithFlags(&s1, cudaStreamNonBlocking);
        cudaEventCreateWithFlags(&evFork, cudaEventDisableTiming);
        cudaEventCreateWithFlags(&evW, cudaEventDisableTiming);
        cudaEventCreateWithFlags(&evJoin, cudaEventDisableTiming);
    }
};
SideStream g_ss;
}

extern "C" void kernel_launch(void* const* d_in, const int* in_sizes, int n_in,
                              void* d_out, int out_size) {
    const float* x = (const float*)d_in[0];
    int base = (in_sizes[1] == 1) ? 3 : 1;
    const float* mk    = (const float*)d_in[base + 0];
    const float* mv    = (const float*)d_in[base + 1];
    const float* mr    = (const float*)d_in[base + 2];
    const float* Wk    = (const float*)d_in[base + 3];
    const float* Wv    = (const float*)d_in[base + 4];
    const float* Wr    = (const float*)d_in[base + 5];
    const float* Wo    = (const float*)d_in[base + 6];
    const float* sd    = (const float*)d_in[base + 7];
    const float* sf    = (const float*)d_in[base + 8];
    const float* cvw   = (const float*)d_in[base + 9];
    const float* cvb   = (const float*)d_in[base + 10];
    const float* bns_v = (const float*)d_in[base + 11];
    const float* bnb_v = (const float*)d_in[base + 12];
    const float* chw   = (const float*)d_in[base + 13];
    const float* chb   = (const float*)d_in[base + 14];
    const float* bns_h = (const float*)d_in[base + 15];
    const float* bnb_h = (const float*)d_in[base + 16];

    cudaFuncSetAttribute(gemm1_kernel, cudaFuncAttributeMaxDynamicSharedMemorySize, GEMM1_SMEM);

    // fork at entry: side stream runs weights + conv + peak
    cudaEventRecord(g_ss.evFork, 0);
    cudaStreamWaitEvent(g_ss.s1, g_ss.evFork, 0);
    prepw_kernel<<<688, 384, 0, g_ss.s1>>>(mk, mv, mr, Wk, Wv, Wr, Wo, cvw, chw);
    cudaEventRecord(g_ss.evW, g_ss.s1);
    convP_kernel<<<1024, 256, 0, g_ss.s1>>>(x);
    peak_kernel<<<512, 384, 0, g_ss.s1>>>(x, cvb, bns_v, bnb_v, chb, bns_h, bnb_h);
    cudaEventRecord(g_ss.evJoin, g_ss.s1);

    // main: prepa (only needs x), then gemm1 (needs g_Wf from prepw)
    prepa_kernel<<<512, 384>>>(x);
    cudaStreamWaitEvent(0, g_ss.evW, 0);
    gemm1_kernel<<<dim3(64, 6), 256, GEMM1_SMEM>>>();

    // join before wkv (needs peakT + kT + vT)
    cudaStreamWaitEvent(0, g_ss.evJoin, 0);
    wkv_kernel<<<B_*C_, 256>>>(sd, sf);
    gemm2_kernel<<<dim3(256, 3), 128>>>((float*)d_out);
}

// round 15
// speedup vs baseline: 1.1276x; 1.1276x over previous
#include <cuda_runtime.h>
#include <math.h>

#define B_ 2
#define T_ 4096
#define C_ 192
#define NTOT (B_*T_*C_)

// ---------------- scratch ----------------
__device__ float g_Wf[384*576];      // tf32-pre-rounded fused [k|v|r] weights
__device__ float g_Wo[192*192];      // tf32-pre-rounded output weights
__device__ float g_Wp[192*32];       // exact fp32 conv-tap weights
__device__ float g_A[B_*T_*384];     // tf32-pre-rounded [x | qshift(x)]
__device__ float g_P[B_*T_*32];
__device__ float g_peakT[NTOT];      // peak, (B,C,T) layout
__device__ float g_kT[NTOT];
__device__ float g_vT[NTOT];
__device__ float g_yT[NTOT];
__device__ float g_sr[NTOT];

__constant__ float c_prfx[16] = {-2,-2,-2,-2, -2,-1,0,1,  2,2,2,2,  -1,0,1,2};
__constant__ float c_prfy[16] = {-2,-1,0,1,   2,2,2,2,  -1,0,1,2,  -2,-2,-2,-2};

__device__ __forceinline__ unsigned f2tf32(float x) {
    unsigned r;
    asm("cvt.rna.tf32.f32 %0, %1;" : "=r"(r) : "f"(x));
    return r;
}

__device__ __forceinline__ void mma8(float* d, unsigned a0, unsigned a1, unsigned a2, unsigned a3,
                                     unsigned b0, unsigned b1) {
    asm volatile(
        "mma.sync.aligned.m16n8k8.row.col.f32.tf32.tf32.f32 "
        "{%0,%1,%2,%3}, {%4,%5,%6,%7}, {%8,%9}, {%0,%1,%2,%3};\n"
        : "+f"(d[0]), "+f"(d[1]), "+f"(d[2]), "+f"(d[3])
        : "r"(a0), "r"(a1), "r"(a2), "r"(a3), "r"(b0), "r"(b1));
}

// ---------------- prep_w: weights only ----------------
__global__ __launch_bounds__(384) void prepw_kernel(const float* __restrict__ mk,
                                                    const float* __restrict__ mv,
                                                    const float* __restrict__ mr,
                                                    const float* __restrict__ Wk,
                                                    const float* __restrict__ Wv,
                                                    const float* __restrict__ Wr,
                                                    const float* __restrict__ Wo,
                                                    const float* __restrict__ cvw,
                                                    const float* __restrict__ chw) {
    int i = blockIdx.x * 384 + threadIdx.x;
    if (i < 384*576) {
        int row = i / 576, n = i % 576;
        int c = row % 192;
        bool second = row >= 192;
        const float* W; float m; int nn;
        if (n < 192)      { W = Wk; m = mk[c]; nn = n; }
        else if (n < 384) { W = Wv; m = mv[c]; nn = n - 192; }
        else              { W = Wr; m = mr[c]; nn = n - 384; }
        float v = (second ? (1.f - m) : m) * W[c*192 + nn];
        g_Wf[i] = __uint_as_float(f2tf32(v));
        return;
    }
    int j = i - 384*576;
    if (j < 192*32) {
        int c = j / 32, n = j % 32;
        float v = 0.f;
        if (n < 14)      v = cvw[(n/7)*C_*7 + c*7 + (n%7)];
        else if (n < 28) { int n2 = n - 14; v = chw[(n2/7)*C_*7 + c*7 + (n2%7)]; }
        g_Wp[j] = v;
        return;
    }
    int jj = j - 192*32;
    if (jj < 192*192)
        g_Wo[jj] = __uint_as_float(f2tf32(Wo[jj]));
}

// ---------------- prep_A (vectorized): g_A = tf32([x | qshift(x)]) ----------------
__global__ __launch_bounds__(384) void prepa_kernel(const float* __restrict__ x) {
    const float4* x4 = (const float4*)x;
    float4* A4 = (float4*)g_A;
    int tb = blockIdx.x * 16;                 // 512 blocks x 16 tokens
    int j0 = threadIdx.x / 96;                // 0..3
    int f4 = threadIdx.x % 96;                // float4 index within 384-ch row
    bool shifted = f4 >= 48;
    int c4f = shifted ? (f4 - 48) : f4;       // 0..47 float4 within 192 ch
    int g = c4f / 12;                         // 48-ch group
#pragma unroll
    for (int rep = 0; rep < 4; rep++) {
        int gt = tb + j0 + rep*4;
        float4 v;
        if (!shifted) {
            v = x4[(size_t)gt*48 + c4f];
        } else {
            int tt = gt & 4095;
            int hh = tt >> 6, ww = tt & 63;
            int src; bool ok;
            if (g == 0)      { ok = (ww >= 1);  src = gt - 1; }
            else if (g == 1) { ok = (ww <= 62); src = gt + 1; }
            else if (g == 2) { ok = (hh >= 1);  src = gt - 64; }
            else             { ok = (hh <= 62); src = gt + 64; }
            v = ok ? x4[(size_t)src*48 + c4f] : make_float4(0.f, 0.f, 0.f, 0.f);
        }
        float4 o;
        o.x = __uint_as_float(f2tf32(v.x));
        o.y = __uint_as_float(f2tf32(v.y));
        o.z = __uint_as_float(f2tf32(v.z));
        o.w = __uint_as_float(f2tf32(v.w));
        A4[(size_t)gt*96 + f4] = o;
    }
}

// ---------------- convP: g_P = x @ Wp (fp32 exact) ----------------
__global__ __launch_bounds__(256) void convP_kernel(const float* __restrict__ x) {
    __shared__ float xs[8][193];
    int tid = threadIdx.x;
    int tok0 = blockIdx.x * 8;
    for (int i = tid; i < 8*192; i += 256) {
        int r = i / 192, c = i % 192;
        xs[r][c] = x[(size_t)(tok0 + r)*C_ + c];
    }
    __syncthreads();
    int r = tid >> 5, n = tid & 31;
    if (n < 28) {
        float acc = 0.f;
#pragma unroll 8
        for (int c = 0; c < 192; c++)
            acc = fmaf(xs[r][c], g_Wp[c*32 + n], acc);
        g_P[(size_t)(tok0 + r)*32 + n] = acc;
    }
}

// ---------------- adaptive peak -> transposed output (B,C,T) ----------------
__global__ __launch_bounds__(384) void peak_kernel(const float* __restrict__ x,
                                                   const float* __restrict__ cvb,
                                                   const float* __restrict__ bns_v,
                                                   const float* __restrict__ bnb_v,
                                                   const float* __restrict__ chb,
                                                   const float* __restrict__ bns_h,
                                                   const float* __restrict__ bnb_h) {
    int bi = blockIdx.x;                  // 512 blocks
    int b = bi >> 8;
    int tb = (bi & 255) * 16;
    int hh = tb >> 6, wwb = tb & 63;
    __shared__ float gbv[16][4];
    __shared__ int   s_lt[16][16], s_rb[16][16];
    __shared__ float s_wlt[16][16], s_wrb[16][16];
    __shared__ float st[192*17];          // [channel][token] stage, pad 17
    int tid = threadIdx.x;

    if (tid < 64) {
        int j = tid >> 2, dir = tid & 3;
        int ww = wwb + j;
        const float* Pb = g_P + (size_t)b * T_ * 32;
        float s = 0.f;
        if (dir < 2) {
#pragma unroll
            for (int r = 0; r < 7; r++) {
                int hy = hh + r - 3;
                if (hy >= 0 && hy < 64) s += Pb[(size_t)(hy*64 + ww)*32 + dir*7 + r];
            }
        } else {
#pragma unroll
            for (int r = 0; r < 7; r++) {
                int wy = ww + r - 3;
                if (wy >= 0 && wy < 64) s += Pb[(size_t)(hh*64 + wy)*32 + (dir-2)*7 + 14 + r];
            }
        }
        const float inv = rsqrtf(1.f + 1e-5f);
        float bias, scale, shift;
        if (dir == 0)      { bias = cvb[0]; scale = bns_v[0]; shift = bnb_v[0]; }
        else if (dir == 1) { bias = cvb[1]; scale = bns_v[1]; shift = bnb_v[1]; }
        else if (dir == 2) { bias = chb[0]; scale = bns_h[0]; shift = bnb_h[0]; }
        else               { bias = chb[1]; scale = bns_h[1]; shift = bnb_h[1]; }
        float val = (s + bias) * (scale * inv) + shift;
        gbv[j][dir] = 2.f / (1.f + expf(-val));
    }
    __syncthreads();

    if (tid < 256) {
        int j = tid >> 4, o = tid & 15;
        int ww = wwb + j;
        int blk = o >> 2;
        float mx = 0.f, my = 0.f;
        if (blk == 0)      mx = -gbv[j][0];
        else if (blk == 1) my =  gbv[j][3];
        else if (blk == 2) mx =  gbv[j][1];
        else               my = -gbv[j][2];
        float px = (float)(hh + 2) + c_prfx[o] + mx;
        float py = (float)(ww + 2) + c_prfy[o] + my;
        float flx = floorf(px), fly = floorf(py);
        float qltx = fminf(fmaxf(flx,     0.f), 67.f);
        float qlty = fminf(fmaxf(fly,     0.f), 67.f);
        float qrbx = fminf(fmaxf(flx+1.f, 0.f), 67.f);
        float qrby = fminf(fmaxf(fly+1.f, 0.f), 67.f);
        float pxc  = fminf(fmaxf(px,      0.f), 67.f);
        float pyc  = fminf(fmaxf(py,      0.f), 67.f);
        float glt = (1.f + (qltx - pxc)) * (1.f + (qlty - pyc));
        float grb = (1.f - (qrbx - pxc)) * (1.f - (qrby - pyc));
        int rlt = min(max((int)qltx - 2, 0), 63);
        int clt = min(max((int)qlty - 2, 0), 63);
        int rrb = min(max((int)qrbx - 2, 0), 63);
        int crb = min(max((int)qrby - 2, 0), 63);
        s_lt[j][o] = rlt*64 + clt;  s_rb[j][o] = rrb*64 + crb;
        s_wlt[j][o] = glt;          s_wrb[j][o] = grb;
    }
    __syncthreads();

    const float* xb = x + (size_t)b * T_ * C_;
    int slot = tid / 48;
    int c4 = (tid % 48) * 4;
#pragma unroll
    for (int rep = 0; rep < 2; rep++) {
        int j = slot + rep*8;
        float a0 = 0.f, a1 = 0.f, a2 = 0.f, a3 = 0.f;
#pragma unroll
        for (int o = 0; o < 16; o++) {
            float4 a = *(const float4*)&xb[(size_t)s_lt[j][o]*C_ + c4];
            float4 bv = *(const float4*)&xb[(size_t)s_rb[j][o]*C_ + c4];
            float wl = s_wlt[j][o], wr = s_wrb[j][o];
            a0 += wl*a.x + wr*bv.x;
            a1 += wl*a.y + wr*bv.y;
            a2 += wl*a.z + wr*bv.z;
            a3 += wl*a.w + wr*bv.w;
        }
        size_t idx = ((size_t)b*T_ + tb + j)*C_ + c4;
        float4 xc = *(const float4*)&x[idx];
        st[(c4+0)*17 + j] = xc.x - a0*(1.f/16.f);
        st[(c4+1)*17 + j] = xc.y - a1*(1.f/16.f);
        st[(c4+2)*17 + j] = xc.z - a2*(1.f/16.f);
        st[(c4+3)*17 + j] = xc.w - a3*(1.f/16.f);
    }
    __syncthreads();

#pragma unroll
    for (int q = 0; q < 2; q++) {
        int f = tid + q*384;
        int cr = f >> 2;
        int t4 = (f & 3) * 4;
        float4 v;
        v.x = st[cr*17 + t4 + 0];
        v.y = st[cr*17 + t4 + 1];
        v.z = st[cr*17 + t4 + 2];
        v.w = st[cr*17 + t4 + 3];
        *(float4*)&g_peakT[((size_t)(b*C_ + cr))*T_ + tb + t4] = v;
    }
}

// ---------------- fused front GEMM: block 128x96, 8 warps, warp 32x48 ----------------
#define AS1 36
#define BS1 104
#define A_BUF (128*AS1)
#define B_BUF (32*BS1)

__global__ __launch_bounds__(256) void gemm1_kernel() {
    extern __shared__ float smem[];
    float* AsBuf = smem;
    float* BsBuf = smem + 2*A_BUF;

    int tid = threadIdx.x;
    int warp = tid >> 5, lane = tid & 31;
    int bm = blockIdx.x * 128;
    int bny = blockIdx.y;                // 0..5
    int bn = bny * 96;
    int cls = bny >> 1;                  // 0:k 1:v 2:r
    int nloc = (bny & 1) * 96;
    int wm = (warp >> 1) * 32;
    int wn = (warp & 1) * 48;
    int gid = lane >> 2, tig = lane & 3;

    const float* Abase = g_A + (size_t)bm * 384;
    float acc[2][6][4] = {};

    float4 pa[4], pb[3];
#pragma unroll
    for (int q = 0; q < 4; q++) {
        int f = tid + q*256;
        pa[q] = *(const float4*)&Abase[(size_t)(f >> 3)*384 + (f & 7)*4];
    }
#pragma unroll
    for (int q = 0; q < 3; q++) {
        int f = tid + q*256;
        pb[q] = *(const float4*)&g_Wf[(size_t)(f/24)*576 + bn + (f%24)*4];
    }
#pragma unroll
    for (int q = 0; q < 4; q++) {
        int f = tid + q*256;
        *(float4*)&AsBuf[(f >> 3)*AS1 + (f & 7)*4] = pa[q];
    }
#pragma unroll
    for (int q = 0; q < 3; q++) {
        int f = tid + q*256;
        *(float4*)&BsBuf[(f/24)*BS1 + (f%24)*4] = pb[q];
    }
    __syncthreads();

    for (int kc = 0; kc < 12; kc++) {
        int cur = kc & 1;
        if (kc < 11) {
            int k0 = (kc + 1) * 32;
#pragma unroll
            for (int q = 0; q < 4; q++) {
                int f = tid + q*256;
                pa[q] = *(const float4*)&Abase[(size_t)(f >> 3)*384 + k0 + (f & 7)*4];
            }
#pragma unroll
            for (int q = 0; q < 3; q++) {
                int f = tid + q*256;
                pb[q] = *(const float4*)&g_Wf[(size_t)(k0 + f/24)*576 + bn + (f%24)*4];
            }
        }
        const float* as = AsBuf + cur*A_BUF;
        const float* bs = BsBuf + cur*B_BUF;
#pragma unroll
        for (int ks = 0; ks < 4; ks++) {
            int kk0 = ks * 8;
            unsigned afr[2][4], bfr[6][2];
#pragma unroll
            for (int mi = 0; mi < 2; mi++) {
                int rbase = (wm + mi*16 + gid) * AS1;
                afr[mi][0] = __float_as_uint(as[rbase + kk0 + tig]);
                afr[mi][1] = __float_as_uint(as[rbase + 8*AS1 + kk0 + tig]);
                afr[mi][2] = __float_as_uint(as[rbase + kk0 + tig + 4]);
                afr[mi][3] = __float_as_uint(as[rbase + 8*AS1 + kk0 + tig + 4]);
            }
#pragma unroll
            for (int ni = 0; ni < 6; ni++) {
                int col = wn + ni*8 + gid;
                bfr[ni][0] = __float_as_uint(bs[(kk0 + tig)*BS1 + col]);
                bfr[ni][1] = __float_as_uint(bs[(kk0 + tig + 4)*BS1 + col]);
            }
#pragma unroll
            for (int mi = 0; mi < 2; mi++)
#pragma unroll
                for (int ni = 0; ni < 6; ni++)
                    mma8(acc[mi][ni], afr[mi][0], afr[mi][1], afr[mi][2], afr[mi][3],
                         bfr[ni][0], bfr[ni][1]);
        }
        if (kc < 11) {
            __syncthreads();
            int nxt = cur ^ 1;
#pragma unroll
            for (int q = 0; q < 4; q++) {
                int f = tid + q*256;
                *(float4*)&AsBuf[nxt*A_BUF + (f >> 3)*AS1 + (f & 7)*4] = pa[q];
            }
#pragma unroll
            for (int q = 0; q < 3; q++) {
                int f = tid + q*256;
                *(float4*)&BsBuf[nxt*B_BUF + (f/24)*BS1 + (f%24)*4] = pb[q];
            }
            __syncthreads();
        }
    }

    if (cls == 2) {
#pragma unroll
        for (int mi = 0; mi < 2; mi++) {
            int r0 = bm + wm + mi*16 + gid;
#pragma unroll
            for (int ni = 0; ni < 6; ni++) {
                int c0 = nloc + wn + ni*8 + tig*2;
                float v0 = 1.f/(1.f+expf(-acc[mi][ni][0]));
                float v1 = 1.f/(1.f+expf(-acc[mi][ni][1]));
                float v2 = 1.f/(1.f+expf(-acc[mi][ni][2]));
                float v3 = 1.f/(1.f+expf(-acc[mi][ni][3]));
                *(float2*)&g_sr[(size_t)r0*C_ + c0]     = make_float2(v0, v1);
                *(float2*)&g_sr[(size_t)(r0+8)*C_ + c0] = make_float2(v2, v3);
            }
        }
        return;
    }

    // k and v: transpose stage st[channel][token], stride 132
    __syncthreads();
    float* st = smem;
#pragma unroll
    for (int mi = 0; mi < 2; mi++) {
        int r = wm + mi*16 + gid;
#pragma unroll
        for (int ni = 0; ni < 6; ni++) {
            int cc = wn + ni*8 + tig*2;
            st[cc*132 + r]         = acc[mi][ni][0];
            st[(cc+1)*132 + r]     = acc[mi][ni][1];
            st[cc*132 + r + 8]     = acc[mi][ni][2];
            st[(cc+1)*132 + r + 8] = acc[mi][ni][3];
        }
    }
    __syncthreads();
    float* dst = (cls == 0) ? g_kT : g_vT;
    int bb = bm >> 12, trow = bm & 4095;
#pragma unroll
    for (int q = 0; q < 12; q++) {
        int f = q*256 + tid;
        int cr = f >> 5;
        int t4 = (f & 31) * 4;
        float4 v = *(const float4*)&st[cr*132 + t4];
        *(float4*)&dst[((size_t)(bb*C_ + nloc + cr))*T_ + trow + t4] = v;
    }
}

// ---------------- bidirectional WKV scan (v = vT + peakT on load) ----------------
struct Agg { float a, b, dl; };
__device__ __forceinline__ Agg combine(Agg p, Agg s) {
    Agg r;
    r.a  = fmaf(s.dl, p.a, s.a);
    r.b  = fmaf(s.dl, p.b, s.b);
    r.dl = p.dl * s.dl;
    return r;
}
__device__ __forceinline__ Agg shfl_up_agg(Agg v, int off) {
    Agg r;
    r.a  = __shfl_up_sync(0xffffffffu, v.a,  off);
    r.b  = __shfl_up_sync(0xffffffffu, v.b,  off);
    r.dl = __shfl_up_sync(0xffffffffu, v.dl, off);
    return r;
}
__device__ __forceinline__ Agg shfl_dn_agg(Agg v, int off) {
    Agg r;
    r.a  = __shfl_down_sync(0xffffffffu, v.a,  off);
    r.b  = __shfl_down_sync(0xffffffffu, v.b,  off);
    r.dl = __shfl_down_sync(0xffffffffu, v.dl, off);
    return r;
}

__global__ __launch_bounds__(256) void wkv_kernel(const float* __restrict__ sd,
                                                  const float* __restrict__ sf) {
    __shared__ float eks[4352];
    __shared__ float vvs[4352];
    __shared__ Agg warpAgg[8];
    __shared__ Agg warpPre[8];
    int bc = blockIdx.x;
    int c = bc % C_;
    float w  = sd[c] * (1.0f / T_);
    float u  = sf[c] * (1.0f / T_);
    float d  = expf(-w);
    float eu = expf(u);
    float d2 = d*d, d4 = d2*d2, d8 = d4*d4, d16 = d8*d8;
    int tid = threadIdx.x;
    int lane = tid & 31, wid = tid >> 5;
    const float4* kp4 = (const float4*)(g_kT + (size_t)bc * T_);
    const float4* vp4 = (const float4*)(g_vT + (size_t)bc * T_);
    const float4* pk4 = (const float4*)(g_peakT + (size_t)bc * T_);

#pragma unroll
    for (int q = 0; q < 4; q++) {
        int idx = tid + q*256;
        float4 kv = kp4[idx];
        float4 v4 = vp4[idx];
        float4 p4 = pk4[idx];
        v4.x += p4.x; v4.y += p4.y; v4.z += p4.z; v4.w += p4.w;
        int t = idx * 4;
        int base = t + (t >> 4);
        eks[base+0] = expf(kv.x); eks[base+1] = expf(kv.y);
        eks[base+2] = expf(kv.z); eks[base+3] = expf(kv.w);
        vvs[base+0] = v4.x; vvs[base+1] = v4.y;
        vvs[base+2] = v4.z; vvs[base+3] = v4.w;
    }
    __syncthreads();

    float ek[16], vv[16];
    int rb = 17 * tid;
#pragma unroll
    for (int i = 0; i < 16; i++) { ek[i] = eks[rb + i]; vv[i] = vvs[rb + i]; }

    Agg ag; ag.a = 0.f; ag.b = 0.f; ag.dl = d16;
#pragma unroll
    for (int i = 0; i < 16; i++) {
        ag.a = fmaf(d, ag.a, ek[i]);
        ag.b = fmaf(d, ag.b, ek[i]*vv[i]);
    }
    Agg inc = ag;
#pragma unroll
    for (int off = 1; off < 32; off <<= 1) {
        Agg o = shfl_up_agg(inc, off);
        if (lane >= off) inc = combine(o, inc);
    }
    if (lane == 31) warpAgg[wid] = inc;
    __syncthreads();
    if (tid == 0) {
        Agg run; run.a = 0.f; run.b = 0.f; run.dl = 1.f;
        for (int i = 0; i < 8; i++) { warpPre[i] = run; run = combine(run, warpAgg[i]); }
    }
    __syncthreads();
    Agg pl = shfl_up_agg(inc, 1);
    Agg ex = warpPre[wid];
    if (lane > 0) ex = combine(ex, pl);

    float af = ex.a, bf = ex.b;
    float saf[16], sbf[16];
#pragma unroll
    for (int i = 0; i < 16; i++) {
        saf[i] = af; sbf[i] = bf;
        af = fmaf(d, af, ek[i]);
        bf = fmaf(d, bf, ek[i]*vv[i]);
    }
    __syncthreads();

    Agg bg; bg.a = 0.f; bg.b = 0.f; bg.dl = d16;
#pragma unroll
    for (int i = 15; i >= 0; i--) {
        bg.a = fmaf(d, bg.a, ek[i]);
        bg.b = fmaf(d, bg.b, ek[i]*vv[i]);
    }
    Agg binc = bg;
#pragma unroll
    for (int off = 1; off < 32; off <<= 1) {
        Agg o = shfl_dn_agg(binc, off);
        if (lane < 32 - off) binc = combine(o, binc);
    }
    if (lane == 0) warpAgg[wid] = binc;
    __syncthreads();
    if (tid == 0) {
        Agg run; run.a = 0.f; run.b = 0.f; run.dl = 1.f;
        for (int i = 7; i >= 0; i--) { warpPre[i] = run; run = combine(run, warpAgg[i]); }
    }
    __syncthreads();
    Agg bpl = shfl_dn_agg(binc, 1);
    Agg bex = warpPre[wid];
    if (lane < 31) bex = combine(bex, bpl);

    float ab = bex.a, bb = bex.b;
#pragma unroll
    for (int i = 15; i >= 0; i--) {
        float es  = eu * ek[i];
        float num = sbf[i] + bb + es * vv[i];
        float den = saf[i] + ab + es;
        vvs[rb + i] = num / den;
        ab = fmaf(d, ab, ek[i]);
        bb = fmaf(d, bb, ek[i]*vv[i]);
    }
    __syncthreads();

    float4* yp4 = (float4*)(g_yT + (size_t)bc * T_);
#pragma unroll
    for (int q = 0; q < 4; q++) {
        int idx = tid + q*256;
        int t = idx * 4;
        int base = t + (t >> 4);
        yp4[idx] = make_float4(vvs[base+0], vvs[base+1], vvs[base+2], vvs[base+3]);
    }
}

// ---------------- output GEMM: out = (sr .* y) @ Wo, full N=192 per block ----------------
// 256 threads, 8 warps as 2M x 4N (warp tile 16x48), bm=32, A staged once.
#define A2S 197
#define B2S 196
#define A2_BUF (32*A2S)
#define B2_BUF (32*B2S)
#define GEMM2_SMEM ((A2_BUF + 2*B2_BUF) * 4)

__global__ __launch_bounds__(256) void gemm2_kernel(float* __restrict__ out) {
    extern __shared__ float sm2[];
    float* As2 = sm2;                  // 32 x 197
    float* Bs2 = sm2 + A2_BUF;         // 2 x 32 x 196

    int tid = threadIdx.x;
    int warp = tid >> 5, lane = tid & 31;
    int gid = lane >> 2, tig = lane & 3;
    int bm = blockIdx.x * 32;
    int wm = (warp >> 2) * 16;
    int wn = (warp & 3) * 48;
    int bb = bm >> 12, trow = bm & 4095;

    // stage A: yT (c,t) -> As2[t][c]
#pragma unroll
    for (int q = 0; q < 6; q++) {
        int f = q*256 + tid;
        int row = f >> 3;             // channel 0..191
        int t4 = (f & 7) * 4;
        float4 v = *(const float4*)&g_yT[((size_t)(bb*C_ + row))*T_ + trow + t4];
        As2[(t4+0)*A2S + row] = v.x;
        As2[(t4+1)*A2S + row] = v.y;
        As2[(t4+2)*A2S + row] = v.z;
        As2[(t4+3)*A2S + row] = v.w;
    }
    __syncthreads();
    // multiply by sr, round to tf32
#pragma unroll
    for (int q = 0; q < 6; q++) {
        int f = q*256 + tid;
        int t = f / 48, c4 = (f % 48) * 4;
        float4 s = *(const float4*)&g_sr[((size_t)(bm + t))*C_ + c4];
        float* p = &As2[t*A2S + c4];
        p[0] = __uint_as_float(f2tf32(p[0] * s.x));
        p[1] = __uint_as_float(f2tf32(p[1] * s.y));
        p[2] = __uint_as_float(f2tf32(p[2] * s.z));
        p[3] = __uint_as_float(f2tf32(p[3] * s.w));
    }

    float acc[6][4] = {};

    // B prefetch chunk 0 (rows 0..31 of Wo, all 192 cols)
    float4 pb[6];
#pragma unroll
    for (int q = 0; q < 6; q++) {
        int f = q*256 + tid;
        int row = f / 48, c4 = (f % 48) * 4;
        pb[q] = *(const float4*)&g_Wo[(size_t)row*C_ + c4];
    }
#pragma unroll
    for (int q = 0; q < 6; q++) {
        int f = q*256 + tid;
        int row = f / 48, c4 = (f % 48) * 4;
        *(float4*)&Bs2[row*B2S + c4] = pb[q];      // pre-rounded tf32 bits
    }
    __syncthreads();

    for (int kc = 0; kc < 6; kc++) {
        int cur = kc & 1;
        if (kc < 5) {
            int k0 = (kc + 1) * 32;
#pragma unroll
            for (int q = 0; q < 6; q++) {
                int f = q*256 + tid;
                int row = f / 48, c4 = (f % 48) * 4;
                pb[q] = *(const float4*)&g_Wo[(size_t)(k0 + row)*C_ + c4];
            }
        }
        const float* bs = Bs2 + cur*B2_BUF;
        int k0 = kc * 32;
#pragma unroll
        for (int ks = 0; ks < 4; ks++) {
            int kk = k0 + ks*8;
            unsigned a0 = __float_as_uint(As2[(wm+gid)*A2S + kk + tig]);
            unsigned a1 = __float_as_uint(As2[(wm+gid+8)*A2S + kk + tig]);
            unsigned a2 = __float_as_uint(As2[(wm+gid)*A2S + kk + tig + 4]);
            unsigned a3 = __float_as_uint(As2[(wm+gid+8)*A2S + kk + tig + 4]);
#pragma unroll
            for (int ni = 0; ni < 6; ni++) {
                int col = wn + ni*8 + gid;
                unsigned b0 = __float_as_uint(bs[(ks*8 + tig)*B2S + col]);
                unsigned b1 = __float_as_uint(bs[(ks*8 + tig + 4)*B2S + col]);
                mma8(acc[ni], a0, a1, a2, a3, b0, b1);
            }
        }
        if (kc < 5) {
            __syncthreads();
            int nxt = cur ^ 1;
#pragma unroll
            for (int q = 0; q < 6; q++) {
                int f = q*256 + tid;
                int row = f / 48, c4 = (f % 48) * 4;
                *(float4*)&Bs2[nxt*B2_BUF + row*B2S + c4] = pb[q];
            }
            __syncthreads();
        }
    }

    int r0 = bm + wm + gid;
#pragma unroll
    for (int ni = 0; ni < 6; ni++) {
        int c0 = wn + ni*8 + tig*2;
        *(float2*)&out[(size_t)r0*C_ + c0]     = make_float2(acc[ni][0], acc[ni][1]);
        *(float2*)&out[(size_t)(r0+8)*C_ + c0] = make_float2(acc[ni][2], acc[ni][3]);
    }
}

// ---------------- launch (R11 topology) ----------------
// main:  prepw -> fork -> prepa -> gemm1 -> [wait evJoin] wkv -> gemm2
// side:  convP -> peak
#define GEMM1_SMEM ((2*A_BUF + 2*B_BUF) * 4)

namespace {
struct SideStream {
    cudaStream_t s1;
    cudaEvent_t evFork, evJoin;
    SideStream() {
        cudaStreamCreateWithFlags(&s1, cudaStreamNonBlocking);
        cudaEventCreateWithFlags(&evFork, cudaEventDisableTiming);
        cudaEventCreateWithFlags(&evJoin, cudaEventDisableTiming);
    }
};
SideStream g_ss;
}

extern "C" void kernel_launch(void* const* d_in, const int* in_sizes, int n_in,
                              void* d_out, int out_size) {
    const float* x = (const float*)d_in[0];
    int base = (in_sizes[1] == 1) ? 3 : 1;
    const float* mk    = (const float*)d_in[base + 0];
    const float* mv    = (const float*)d_in[base + 1];
    const float* mr    = (const float*)d_in[base + 2];
    const float* Wk    = (const float*)d_in[base + 3];
    const float* Wv    = (const float*)d_in[base + 4];
    const float* Wr    = (const float*)d_in[base + 5];
    const float* Wo    = (const float*)d_in[base + 6];
    const float* sd    = (const float*)d_in[base + 7];
    const float* sf    = (const float*)d_in[base + 8];
    const float* cvw   = (const float*)d_in[base + 9];
    const float* cvb   = (const float*)d_in[base + 10];
    const float* bns_v = (const float*)d_in[base + 11];
    const float* bnb_v = (const float*)d_in[base + 12];
    const float* chw   = (const float*)d_in[base + 13];
    const float* chb   = (const float*)d_in[base + 14];
    const float* bns_h = (const float*)d_in[base + 15];
    const float* bnb_h = (const float*)d_in[base + 16];

    cudaFuncSetAttribute(gemm1_kernel, cudaFuncAttributeMaxDynamicSharedMemorySize, GEMM1_SMEM);
    cudaFuncSetAttribute(gemm2_kernel, cudaFuncAttributeMaxDynamicSharedMemorySize, GEMM2_SMEM);

    // weights (needed by both branches) — serial on main stream (R11 topology)
    prepw_kernel<<<688, 384>>>(mk, mv, mr, Wk, Wv, Wr, Wo, cvw, chw);

    // fork
    cudaEventRecord(g_ss.evFork, 0);
    cudaStreamWaitEvent(g_ss.s1, g_ss.evFork, 0);

    // side: convP -> peak (produces g_peakT, needed only by wkv)
    convP_kernel<<<1024, 256, 0, g_ss.s1>>>(x);
    peak_kernel<<<512, 384, 0, g_ss.s1>>>(x, cvb, bns_v, bnb_v, chb, bns_h, bnb_h);
    cudaEventRecord(g_ss.evJoin, g_ss.s1);

    // main: prepa -> gemm1
    prepa_kernel<<<512, 384>>>(x);
    gemm1_kernel<<<dim3(64, 6), 256, GEMM1_SMEM>>>();

    // join before wkv (needs peakT + kT + vT)
    cudaStreamWaitEvent(0, g_ss.evJoin, 0);
    wkv_kernel<<<B_*C_, 256>>>(sd, sf);
    gemm2_kernel<<<256, 256, GEMM2_SMEM>>>((float*)d_out);
}

// round 16
// speedup vs baseline: 1.1549x; 1.0242x over previous
#include <cuda_runtime.h>
#include <math.h>

#define B_ 2
#define T_ 4096
#define C_ 192
#define NTOT (B_*T_*C_)

// ---------------- scratch ----------------
__device__ float g_Wf[384*576];      // tf32-pre-rounded fused [k|v|r] weights
__device__ float g_Wo[192*192];      // tf32-pre-rounded output weights
__device__ float g_Wp[192*32];       // exact fp32 conv-tap weights
__device__ float g_A[B_*T_*384];     // tf32-pre-rounded [x | qshift(x)]
__device__ float g_P[B_*T_*32];
__device__ float g_peakT[NTOT];      // peak, (B,C,T) layout
__device__ float g_kT[NTOT];
__device__ float g_vT[NTOT];
__device__ float g_yT[NTOT];
__device__ float g_sr[NTOT];

__constant__ float c_prfx[16] = {-2,-2,-2,-2, -2,-1,0,1,  2,2,2,2,  -1,0,1,2};
__constant__ float c_prfy[16] = {-2,-1,0,1,   2,2,2,2,  -1,0,1,2,  -2,-2,-2,-2};

__device__ __forceinline__ unsigned f2tf32(float x) {
    unsigned r;
    asm("cvt.rna.tf32.f32 %0, %1;" : "=r"(r) : "f"(x));
    return r;
}

__device__ __forceinline__ void mma8(float* d, unsigned a0, unsigned a1, unsigned a2, unsigned a3,
                                     unsigned b0, unsigned b1) {
    asm volatile(
        "mma.sync.aligned.m16n8k8.row.col.f32.tf32.tf32.f32 "
        "{%0,%1,%2,%3}, {%4,%5,%6,%7}, {%8,%9}, {%0,%1,%2,%3};\n"
        : "+f"(d[0]), "+f"(d[1]), "+f"(d[2]), "+f"(d[3])
        : "r"(a0), "r"(a1), "r"(a2), "r"(a3), "r"(b0), "r"(b1));
}

// ---------------- prep_w: weights only ----------------
__global__ __launch_bounds__(384) void prepw_kernel(const float* __restrict__ mk,
                                                    const float* __restrict__ mv,
                                                    const float* __restrict__ mr,
                                                    const float* __restrict__ Wk,
                                                    const float* __restrict__ Wv,
                                                    const float* __restrict__ Wr,
                                                    const float* __restrict__ Wo,
                                                    const float* __restrict__ cvw,
                                                    const float* __restrict__ chw) {
    int i = blockIdx.x * 384 + threadIdx.x;
    if (i < 384*576) {
        int row = i / 576, n = i % 576;
        int c = row % 192;
        bool second = row >= 192;
        const float* W; float m; int nn;
        if (n < 192)      { W = Wk; m = mk[c]; nn = n; }
        else if (n < 384) { W = Wv; m = mv[c]; nn = n - 192; }
        else              { W = Wr; m = mr[c]; nn = n - 384; }
        float v = (second ? (1.f - m) : m) * W[c*192 + nn];
        g_Wf[i] = __uint_as_float(f2tf32(v));
        return;
    }
    int j = i - 384*576;
    if (j < 192*32) {
        int c = j / 32, n = j % 32;
        float v = 0.f;
        if (n < 14)      v = cvw[(n/7)*C_*7 + c*7 + (n%7)];
        else if (n < 28) { int n2 = n - 14; v = chw[(n2/7)*C_*7 + c*7 + (n2%7)]; }
        g_Wp[j] = v;
        return;
    }
    int jj = j - 192*32;
    if (jj < 192*192)
        g_Wo[jj] = __uint_as_float(f2tf32(Wo[jj]));
}

// ---------------- prep_A (vectorized, 4 tokens/block): g_A = tf32([x | qshift(x)]) ----------------
__global__ __launch_bounds__(384) void prepa_kernel(const float* __restrict__ x) {
    const float4* x4 = (const float4*)x;
    float4* A4 = (float4*)g_A;
    int gt = blockIdx.x * 4 + threadIdx.x / 96;   // 2048 blocks x 4 tokens
    int f4 = threadIdx.x % 96;                    // float4 index within 384-ch row
    bool shifted = f4 >= 48;
    int c4f = shifted ? (f4 - 48) : f4;
    int g = c4f / 12;
    float4 v;
    if (!shifted) {
        v = x4[(size_t)gt*48 + c4f];
    } else {
        int tt = gt & 4095;
        int hh = tt >> 6, ww = tt & 63;
        int src; bool ok;
        if (g == 0)      { ok = (ww >= 1);  src = gt - 1; }
        else if (g == 1) { ok = (ww <= 62); src = gt + 1; }
        else if (g == 2) { ok = (hh >= 1);  src = gt - 64; }
        else             { ok = (hh <= 62); src = gt + 64; }
        v = ok ? x4[(size_t)src*48 + c4f] : make_float4(0.f, 0.f, 0.f, 0.f);
    }
    float4 o;
    o.x = __uint_as_float(f2tf32(v.x));
    o.y = __uint_as_float(f2tf32(v.y));
    o.z = __uint_as_float(f2tf32(v.z));
    o.w = __uint_as_float(f2tf32(v.w));
    A4[(size_t)gt*96 + f4] = o;
}

// ---------------- convP: g_P = x @ Wp (fp32 exact) ----------------
__global__ __launch_bounds__(256) void convP_kernel(const float* __restrict__ x) {
    __shared__ float xs[8][193];
    int tid = threadIdx.x;
    int tok0 = blockIdx.x * 8;
    for (int i = tid; i < 8*192; i += 256) {
        int r = i / 192, c = i % 192;
        xs[r][c] = x[(size_t)(tok0 + r)*C_ + c];
    }
    __syncthreads();
    int r = tid >> 5, n = tid & 31;
    if (n < 28) {
        float acc = 0.f;
#pragma unroll 8
        for (int c = 0; c < 192; c++)
            acc = fmaf(xs[r][c], g_Wp[c*32 + n], acc);
        g_P[(size_t)(tok0 + r)*32 + n] = acc;
    }
}

// ---------------- adaptive peak -> transposed output (B,C,T) ----------------
__global__ __launch_bounds__(384) void peak_kernel(const float* __restrict__ x,
                                                   const float* __restrict__ cvb,
                                                   const float* __restrict__ bns_v,
                                                   const float* __restrict__ bnb_v,
                                                   const float* __restrict__ chb,
                                                   const float* __restrict__ bns_h,
                                                   const float* __restrict__ bnb_h) {
    int bi = blockIdx.x;                  // 512 blocks
    int b = bi >> 8;
    int tb = (bi & 255) * 16;
    int hh = tb >> 6, wwb = tb & 63;
    __shared__ float gbv[16][4];
    __shared__ int   s_lt[16][16], s_rb[16][16];
    __shared__ float s_wlt[16][16], s_wrb[16][16];
    __shared__ float st[192*17];
    int tid = threadIdx.x;

    if (tid < 64) {
        int j = tid >> 2, dir = tid & 3;
        int ww = wwb + j;
        const float* Pb = g_P + (size_t)b * T_ * 32;
        float s = 0.f;
        if (dir < 2) {
#pragma unroll
            for (int r = 0; r < 7; r++) {
                int hy = hh + r - 3;
                if (hy >= 0 && hy < 64) s += Pb[(size_t)(hy*64 + ww)*32 + dir*7 + r];
            }
        } else {
#pragma unroll
            for (int r = 0; r < 7; r++) {
                int wy = ww + r - 3;
                if (wy >= 0 && wy < 64) s += Pb[(size_t)(hh*64 + wy)*32 + (dir-2)*7 + 14 + r];
            }
        }
        const float inv = rsqrtf(1.f + 1e-5f);
        float bias, scale, shift;
        if (dir == 0)      { bias = cvb[0]; scale = bns_v[0]; shift = bnb_v[0]; }
        else if (dir == 1) { bias = cvb[1]; scale = bns_v[1]; shift = bnb_v[1]; }
        else if (dir == 2) { bias = chb[0]; scale = bns_h[0]; shift = bnb_h[0]; }
        else               { bias = chb[1]; scale = bns_h[1]; shift = bnb_h[1]; }
        float val = (s + bias) * (scale * inv) + shift;
        gbv[j][dir] = 2.f / (1.f + expf(-val));
    }
    __syncthreads();

    if (tid < 256) {
        int j = tid >> 4, o = tid & 15;
        int ww = wwb + j;
        int blk = o >> 2;
        float mx = 0.f, my = 0.f;
        if (blk == 0)      mx = -gbv[j][0];
        else if (blk == 1) my =  gbv[j][3];
        else if (blk == 2) mx =  gbv[j][1];
        else               my = -gbv[j][2];
        float px = (float)(hh + 2) + c_prfx[o] + mx;
        float py = (float)(ww + 2) + c_prfy[o] + my;
        float flx = floorf(px), fly = floorf(py);
        float qltx = fminf(fmaxf(flx,     0.f), 67.f);
        float qlty = fminf(fmaxf(fly,     0.f), 67.f);
        float qrbx = fminf(fmaxf(flx+1.f, 0.f), 67.f);
        float qrby = fminf(fmaxf(fly+1.f, 0.f), 67.f);
        float pxc  = fminf(fmaxf(px,      0.f), 67.f);
        float pyc  = fminf(fmaxf(py,      0.f), 67.f);
        float glt = (1.f + (qltx - pxc)) * (1.f + (qlty - pyc));
        float grb = (1.f - (qrbx - pxc)) * (1.f - (qrby - pyc));
        int rlt = min(max((int)qltx - 2, 0), 63);
        int clt = min(max((int)qlty - 2, 0), 63);
        int rrb = min(max((int)qrbx - 2, 0), 63);
        int crb = min(max((int)qrby - 2, 0), 63);
        s_lt[j][o] = rlt*64 + clt;  s_rb[j][o] = rrb*64 + crb;
        s_wlt[j][o] = glt;          s_wrb[j][o] = grb;
    }
    __syncthreads();

    const float* xb = x + (size_t)b * T_ * C_;
    int slot = tid / 48;
    int c4 = (tid % 48) * 4;
#pragma unroll
    for (int rep = 0; rep < 2; rep++) {
        int j = slot + rep*8;
        float a0 = 0.f, a1 = 0.f, a2 = 0.f, a3 = 0.f;
#pragma unroll
        for (int o = 0; o < 16; o++) {
            float4 a = *(const float4*)&xb[(size_t)s_lt[j][o]*C_ + c4];
            float4 bv = *(const float4*)&xb[(size_t)s_rb[j][o]*C_ + c4];
            float wl = s_wlt[j][o], wr = s_wrb[j][o];
            a0 += wl*a.x + wr*bv.x;
            a1 += wl*a.y + wr*bv.y;
            a2 += wl*a.z + wr*bv.z;
            a3 += wl*a.w + wr*bv.w;
        }
        size_t idx = ((size_t)b*T_ + tb + j)*C_ + c4;
        float4 xc = *(const float4*)&x[idx];
        st[(c4+0)*17 + j] = xc.x - a0*(1.f/16.f);
        st[(c4+1)*17 + j] = xc.y - a1*(1.f/16.f);
        st[(c4+2)*17 + j] = xc.z - a2*(1.f/16.f);
        st[(c4+3)*17 + j] = xc.w - a3*(1.f/16.f);
    }
    __syncthreads();

#pragma unroll
    for (int q = 0; q < 2; q++) {
        int f = tid + q*384;
        int cr = f >> 2;
        int t4 = (f & 3) * 4;
        float4 v;
        v.x = st[cr*17 + t4 + 0];
        v.y = st[cr*17 + t4 + 1];
        v.z = st[cr*17 + t4 + 2];
        v.w = st[cr*17 + t4 + 3];
        *(float4*)&g_peakT[((size_t)(b*C_ + cr))*T_ + tb + t4] = v;
    }
}

// ---------------- fused front GEMM: block 128x96, 8 warps, warp 32x48, single-sync DB ----------------
#define AS1 36
#define BS1 104
#define A_BUF (128*AS1)
#define B_BUF (32*BS1)

__device__ __forceinline__ void g1_load(const float* __restrict__ Abase, int bn, int k0,
                                        int tid, float4* pa, float4* pb) {
#pragma unroll
    for (int q = 0; q < 4; q++) {
        int f = tid + q*256;
        pa[q] = *(const float4*)&Abase[(size_t)(f >> 3)*384 + k0 + (f & 7)*4];
    }
#pragma unroll
    for (int q = 0; q < 3; q++) {
        int f = tid + q*256;
        pb[q] = *(const float4*)&g_Wf[(size_t)(k0 + f/24)*576 + bn + (f%24)*4];
    }
}

__device__ __forceinline__ void g1_store(float* AsBuf, float* BsBuf, int tid,
                                         const float4* pa, const float4* pb) {
#pragma unroll
    for (int q = 0; q < 4; q++) {
        int f = tid + q*256;
        *(float4*)&AsBuf[(f >> 3)*AS1 + (f & 7)*4] = pa[q];
    }
#pragma unroll
    for (int q = 0; q < 3; q++) {
        int f = tid + q*256;
        *(float4*)&BsBuf[(f/24)*BS1 + (f%24)*4] = pb[q];
    }
}

__global__ __launch_bounds__(256) void gemm1_kernel() {
    extern __shared__ float smem[];
    float* AsBuf = smem;
    float* BsBuf = smem + 2*A_BUF;

    int tid = threadIdx.x;
    int warp = tid >> 5, lane = tid & 31;
    int bm = blockIdx.x * 128;
    int bny = blockIdx.y;                // 0..5
    int bn = bny * 96;
    int cls = bny >> 1;                  // 0:k 1:v 2:r
    int nloc = (bny & 1) * 96;
    int wm = (warp >> 1) * 32;
    int wn = (warp & 1) * 48;
    int gid = lane >> 2, tig = lane & 3;

    const float* Abase = g_A + (size_t)bm * 384;
    float acc[2][6][4] = {};

    float4 pa[4], pb[3];
    // prologue: chunk0 -> buf0; sync; load chunk1
    g1_load(Abase, bn, 0, tid, pa, pb);
    g1_store(AsBuf, BsBuf, tid, pa, pb);
    __syncthreads();
    g1_load(Abase, bn, 32, tid, pa, pb);

    for (int kc = 0; kc < 12; kc++) {
        int cur = kc & 1;
        const float* as = AsBuf + cur*A_BUF;
        const float* bs = BsBuf + cur*B_BUF;
#pragma unroll
        for (int ks = 0; ks < 4; ks++) {
            int kk0 = ks * 8;
            unsigned afr[2][4], bfr[6][2];
#pragma unroll
            for (int mi = 0; mi < 2; mi++) {
                int rbase = (wm + mi*16 + gid) * AS1;
                afr[mi][0] = __float_as_uint(as[rbase + kk0 + tig]);
                afr[mi][1] = __float_as_uint(as[rbase + 8*AS1 + kk0 + tig]);
                afr[mi][2] = __float_as_uint(as[rbase + kk0 + tig + 4]);
                afr[mi][3] = __float_as_uint(as[rbase + 8*AS1 + kk0 + tig + 4]);
            }
#pragma unroll
            for (int ni = 0; ni < 6; ni++) {
                int col = wn + ni*8 + gid;
                bfr[ni][0] = __float_as_uint(bs[(kk0 + tig)*BS1 + col]);
                bfr[ni][1] = __float_as_uint(bs[(kk0 + tig + 4)*BS1 + col]);
            }
#pragma unroll
            for (int mi = 0; mi < 2; mi++)
#pragma unroll
                for (int ni = 0; ni < 6; ni++)
                    mma8(acc[mi][ni], afr[mi][0], afr[mi][1], afr[mi][2], afr[mi][3],
                         bfr[ni][0], bfr[ni][1]);
        }
        if (kc < 11) {
            // store chunk kc+1 (held in regs) into the OTHER buffer; its last
            // readers were fenced by the previous iteration's __syncthreads().
            int nxt = cur ^ 1;
            g1_store(AsBuf + nxt*A_BUF, BsBuf + nxt*B_BUF, tid, pa, pb);
            __syncthreads();
            if (kc < 10) g1_load(Abase, bn, (kc + 2) * 32, tid, pa, pb);
        }
    }

    if (cls == 2) {
#pragma unroll
        for (int mi = 0; mi < 2; mi++) {
            int r0 = bm + wm + mi*16 + gid;
#pragma unroll
            for (int ni = 0; ni < 6; ni++) {
                int c0 = nloc + wn + ni*8 + tig*2;
                float v0 = 1.f/(1.f+expf(-acc[mi][ni][0]));
                float v1 = 1.f/(1.f+expf(-acc[mi][ni][1]));
                float v2 = 1.f/(1.f+expf(-acc[mi][ni][2]));
                float v3 = 1.f/(1.f+expf(-acc[mi][ni][3]));
                *(float2*)&g_sr[(size_t)r0*C_ + c0]     = make_float2(v0, v1);
                *(float2*)&g_sr[(size_t)(r0+8)*C_ + c0] = make_float2(v2, v3);
            }
        }
        return;
    }

    // k and v: transpose stage st[channel][token], stride 132
    __syncthreads();
    float* st = smem;
#pragma unroll
    for (int mi = 0; mi < 2; mi++) {
        int r = wm + mi*16 + gid;
#pragma unroll
        for (int ni = 0; ni < 6; ni++) {
            int cc = wn + ni*8 + tig*2;
            st[cc*132 + r]         = acc[mi][ni][0];
            st[(cc+1)*132 + r]     = acc[mi][ni][1];
            st[cc*132 + r + 8]     = acc[mi][ni][2];
            st[(cc+1)*132 + r + 8] = acc[mi][ni][3];
        }
    }
    __syncthreads();
    float* dst = (cls == 0) ? g_kT : g_vT;
    int bb = bm >> 12, trow = bm & 4095;
#pragma unroll
    for (int q = 0; q < 12; q++) {
        int f = q*256 + tid;
        int cr = f >> 5;
        int t4 = (f & 31) * 4;
        float4 v = *(const float4*)&st[cr*132 + t4];
        *(float4*)&dst[((size_t)(bb*C_ + nloc + cr))*T_ + trow + t4] = v;
    }
}

// ---------------- bidirectional WKV scan (v = vT + peakT on load) ----------------
struct Agg { float a, b, dl; };
__device__ __forceinline__ Agg combine(Agg p, Agg s) {
    Agg r;
    r.a  = fmaf(s.dl, p.a, s.a);
    r.b  = fmaf(s.dl, p.b, s.b);
    r.dl = p.dl * s.dl;
    return r;
}
__device__ __forceinline__ Agg shfl_up_agg(Agg v, int off) {
    Agg r;
    r.a  = __shfl_up_sync(0xffffffffu, v.a,  off);
    r.b  = __shfl_up_sync(0xffffffffu, v.b,  off);
    r.dl = __shfl_up_sync(0xffffffffu, v.dl, off);
    return r;
}
__device__ __forceinline__ Agg shfl_dn_agg(Agg v, int off) {
    Agg r;
    r.a  = __shfl_down_sync(0xffffffffu, v.a,  off);
    r.b  = __shfl_down_sync(0xffffffffu, v.b,  off);
    r.dl = __shfl_down_sync(0xffffffffu, v.dl, off);
    return r;
}

__global__ __launch_bounds__(256) void wkv_kernel(const float* __restrict__ sd,
                                                  const float* __restrict__ sf) {
    __shared__ float eks[4352];
    __shared__ float vvs[4352];
    __shared__ Agg warpAgg[8];
    __shared__ Agg warpPre[8];
    int bc = blockIdx.x;
    int c = bc % C_;
    float w  = sd[c] * (1.0f / T_);
    float u  = sf[c] * (1.0f / T_);
    float d  = expf(-w);
    float eu = expf(u);
    float d2 = d*d, d4 = d2*d2, d8 = d4*d4, d16 = d8*d8;
    int tid = threadIdx.x;
    int lane = tid & 31, wid = tid >> 5;
    const float4* kp4 = (const float4*)(g_kT + (size_t)bc * T_);
    const float4* vp4 = (const float4*)(g_vT + (size_t)bc * T_);
    const float4* pk4 = (const float4*)(g_peakT + (size_t)bc * T_);

#pragma unroll
    for (int q = 0; q < 4; q++) {
        int idx = tid + q*256;
        float4 kv = kp4[idx];
        float4 v4 = vp4[idx];
        float4 p4 = pk4[idx];
        v4.x += p4.x; v4.y += p4.y; v4.z += p4.z; v4.w += p4.w;
        int t = idx * 4;
        int base = t + (t >> 4);
        eks[base+0] = expf(kv.x); eks[base+1] = expf(kv.y);
        eks[base+2] = expf(kv.z); eks[base+3] = expf(kv.w);
        vvs[base+0] = v4.x; vvs[base+1] = v4.y;
        vvs[base+2] = v4.z; vvs[base+3] = v4.w;
    }
    __syncthreads();

    float ek[16], vv[16];
    int rb = 17 * tid;
#pragma unroll
    for (int i = 0; i < 16; i++) { ek[i] = eks[rb + i]; vv[i] = vvs[rb + i]; }

    Agg ag; ag.a = 0.f; ag.b = 0.f; ag.dl = d16;
#pragma unroll
    for (int i = 0; i < 16; i++) {
        ag.a = fmaf(d, ag.a, ek[i]);
        ag.b = fmaf(d, ag.b, ek[i]*vv[i]);
    }
    Agg inc = ag;
#pragma unroll
    for (int off = 1; off < 32; off <<= 1) {
        Agg o = shfl_up_agg(inc, off);
        if (lane >= off) inc = combine(o, inc);
    }
    if (lane == 31) warpAgg[wid] = inc;
    __syncthreads();
    if (tid == 0) {
        Agg run; run.a = 0.f; run.b = 0.f; run.dl = 1.f;
        for (int i = 0; i < 8; i++) { warpPre[i] = run; run = combine(run, warpAgg[i]); }
    }
    __syncthreads();
    Agg pl = shfl_up_agg(inc, 1);
    Agg ex = warpPre[wid];
    if (lane > 0) ex = combine(ex, pl);

    float af = ex.a, bf = ex.b;
    float saf[16], sbf[16];
#pragma unroll
    for (int i = 0; i < 16; i++) {
        saf[i] = af; sbf[i] = bf;
        af = fmaf(d, af, ek[i]);
        bf = fmaf(d, bf, ek[i]*vv[i]);
    }
    __syncthreads();

    Agg bg; bg.a = 0.f; bg.b = 0.f; bg.dl = d16;
#pragma unroll
    for (int i = 15; i >= 0; i--) {
        bg.a = fmaf(d, bg.a, ek[i]);
        bg.b = fmaf(d, bg.b, ek[i]*vv[i]);
    }
    Agg binc = bg;
#pragma unroll
    for (int off = 1; off < 32; off <<= 1) {
        Agg o = shfl_dn_agg(binc, off);
        if (lane < 32 - off) binc = combine(o, binc);
    }
    if (lane == 0) warpAgg[wid] = binc;
    __syncthreads();
    if (tid == 0) {
        Agg run; run.a = 0.f; run.b = 0.f; run.dl = 1.f;
        for (int i = 7; i >= 0; i--) { warpPre[i] = run; run = combine(run, warpAgg[i]); }
    }
    __syncthreads();
    Agg bpl = shfl_dn_agg(binc, 1);
    Agg bex = warpPre[wid];
    if (lane < 31) bex = combine(bex, bpl);

    float ab = bex.a, bb = bex.b;
#pragma unroll
    for (int i = 15; i >= 0; i--) {
        float es  = eu * ek[i];
        float num = sbf[i] + bb + es * vv[i];
        float den = saf[i] + ab + es;
        vvs[rb + i] = num / den;
        ab = fmaf(d, ab, ek[i]);
        bb = fmaf(d, bb, ek[i]*vv[i]);
    }
    __syncthreads();

    float4* yp4 = (float4*)(g_yT + (size_t)bc * T_);
#pragma unroll
    for (int q = 0; q < 4; q++) {
        int idx = tid + q*256;
        int t = idx * 4;
        int base = t + (t >> 4);
        yp4[idx] = make_float4(vvs[base+0], vvs[base+1], vvs[base+2], vvs[base+3]);
    }
}

// ---------------- output GEMM: out = (sr .* y) @ Wo, full N=192 per block ----------------
#define A2S 197
#define B2S 196
#define A2_BUF (32*A2S)
#define B2_BUF (32*B2S)
#define GEMM2_SMEM ((A2_BUF + 2*B2_BUF) * 4)

__global__ __launch_bounds__(256) void gemm2_kernel(float* __restrict__ out) {
    extern __shared__ float sm2[];
    float* As2 = sm2;
    float* Bs2 = sm2 + A2_BUF;

    int tid = threadIdx.x;
    int warp = tid >> 5, lane = tid & 31;
    int gid = lane >> 2, tig = lane & 3;
    int bm = blockIdx.x * 32;
    int wm = (warp >> 2) * 16;
    int wn = (warp & 3) * 48;
    int bb = bm >> 12, trow = bm & 4095;

#pragma unroll
    for (int q = 0; q < 6; q++) {
        int f = q*256 + tid;
        int row = f >> 3;
        int t4 = (f & 7) * 4;
        float4 v = *(const float4*)&g_yT[((size_t)(bb*C_ + row))*T_ + trow + t4];
        As2[(t4+0)*A2S + row] = v.x;
        As2[(t4+1)*A2S + row] = v.y;
        As2[(t4+2)*A2S + row] = v.z;
        As2[(t4+3)*A2S + row] = v.w;
    }
    __syncthreads();
#pragma unroll
    for (int q = 0; q < 6; q++) {
        int f = q*256 + tid;
        int t = f / 48, c4 = (f % 48) * 4;
        float4 s = *(const float4*)&g_sr[((size_t)(bm + t))*C_ + c4];
        float* p = &As2[t*A2S + c4];
        p[0] = __uint_as_float(f2tf32(p[0] * s.x));
        p[1] = __uint_as_float(f2tf32(p[1] * s.y));
        p[2] = __uint_as_float(f2tf32(p[2] * s.z));
        p[3] = __uint_as_float(f2tf32(p[3] * s.w));
    }

    float acc[6][4] = {};

    float4 pb[6];
#pragma unroll
    for (int q = 0; q < 6; q++) {
        int f = q*256 + tid;
        int row = f / 48, c4 = (f % 48) * 4;
        pb[q] = *(const float4*)&g_Wo[(size_t)row*C_ + c4];
    }
#pragma unroll
    for (int q = 0; q < 6; q++) {
        int f = q*256 + tid;
        int row = f / 48, c4 = (f % 48) * 4;
        *(float4*)&Bs2[row*B2S + c4] = pb[q];
    }
    __syncthreads();

    for (int kc = 0; kc < 6; kc++) {
        int cur = kc & 1;
        if (kc < 5) {
            int k0 = (kc + 1) * 32;
#pragma unroll
            for (int q = 0; q < 6; q++) {
                int f = q*256 + tid;
                int row = f / 48, c4 = (f % 48) * 4;
                pb[q] = *(const float4*)&g_Wo[(size_t)(k0 + row)*C_ + c4];
            }
        }
        const float* bs = Bs2 + cur*B2_BUF;
        int k0 = kc * 32;
#pragma unroll
        for (int ks = 0; ks < 4; ks++) {
            int kk = k0 + ks*8;
            unsigned a0 = __float_as_uint(As2[(wm+gid)*A2S + kk + tig]);
            unsigned a1 = __float_as_uint(As2[(wm+gid+8)*A2S + kk + tig]);
            unsigned a2 = __float_as_uint(As2[(wm+gid)*A2S + kk + tig + 4]);
            unsigned a3 = __float_as_uint(As2[(wm+gid+8)*A2S + kk + tig + 4]);
#pragma unroll
            for (int ni = 0; ni < 6; ni++) {
                int col = wn + ni*8 + gid;
                unsigned b0 = __float_as_uint(bs[(ks*8 + tig)*B2S + col]);
                unsigned b1 = __float_as_uint(bs[(ks*8 + tig + 4)*B2S + col]);
                mma8(acc[ni], a0, a1, a2, a3, b0, b1);
            }
        }
        if (kc < 5) {
            __syncthreads();
            int nxt = cur ^ 1;
#pragma unroll
            for (int q = 0; q < 6; q++) {
                int f = q*256 + tid;
                int row = f / 48, c4 = (f % 48) * 4;
                *(float4*)&Bs2[nxt*B2_BUF + row*B2S + c4] = pb[q];
            }
            __syncthreads();
        }
    }

    int r0 = bm + wm + gid;
#pragma unroll
    for (int ni = 0; ni < 6; ni++) {
        int c0 = wn + ni*8 + tig*2;
        *(float2*)&out[(size_t)r0*C_ + c0]     = make_float2(acc[ni][0], acc[ni][1]);
        *(float2*)&out[(size_t)(r0+8)*C_ + c0] = make_float2(acc[ni][2], acc[ni][3]);
    }
}

// ---------------- launch (R11 topology) ----------------
#define GEMM1_SMEM ((2*A_BUF + 2*B_BUF) * 4)

namespace {
struct SideStream {
    cudaStream_t s1;
    cudaEvent_t evFork, evJoin;
    SideStream() {
        cudaStreamCreateWithFlags(&s1, cudaStreamNonBlocking);
        cudaEventCreateWithFlags(&evFork, cudaEventDisableTiming);
        cudaEventCreateWithFlags(&evJoin, cudaEventDisableTiming);
    }
};
SideStream g_ss;
}

extern "C" void kernel_launch(void* const* d_in, const int* in_sizes, int n_in,
                              void* d_out, int out_size) {
    const float* x = (const float*)d_in[0];
    int base = (in_sizes[1] == 1) ? 3 : 1;
    const float* mk    = (const float*)d_in[base + 0];
    const float* mv    = (const float*)d_in[base + 1];
    const float* mr    = (const float*)d_in[base + 2];
    const float* Wk    = (const float*)d_in[base + 3];
    const float* Wv    = (const float*)d_in[base + 4];
    const float* Wr    = (const float*)d_in[base + 5];
    const float* Wo    = (const float*)d_in[base + 6];
    const float* sd    = (const float*)d_in[base + 7];
    const float* sf    = (const float*)d_in[base + 8];
    const float* cvw   = (const float*)d_in[base + 9];
    const float* cvb   = (const float*)d_in[base + 10];
    const float* bns_v = (const float*)d_in[base + 11];
    const float* bnb_v = (const float*)d_in[base + 12];
    const float* chw   = (const float*)d_in[base + 13];
    const float* chb   = (const float*)d_in[base + 14];
    const float* bns_h = (const float*)d_in[base + 15];
    const float* bnb_h = (const float*)d_in[base + 16];

    cudaFuncSetAttribute(gemm1_kernel, cudaFuncAttributeMaxDynamicSharedMemorySize, GEMM1_SMEM);
    cudaFuncSetAttribute(gemm2_kernel, cudaFuncAttributeMaxDynamicSharedMemorySize, GEMM2_SMEM);

    prepw_kernel<<<688, 384>>>(mk, mv, mr, Wk, Wv, Wr, Wo, cvw, chw);

    cudaEventRecord(g_ss.evFork, 0);
    cudaStreamWaitEvent(g_ss.s1, g_ss.evFork, 0);

    convP_kernel<<<1024, 256, 0, g_ss.s1>>>(x);
    peak_kernel<<<512, 384, 0, g_ss.s1>>>(x, cvb, bns_v, bnb_v, chb, bns_h, bnb_h);
    cudaEventRecord(g_ss.evJoin, g_ss.s1);

    prepa_kernel<<<2048, 384>>>(x);
    gemm1_kernel<<<dim3(64, 6), 256, GEMM1_SMEM>>>();

    cudaStreamWaitEvent(0, g_ss.evJoin, 0);
    wkv_kernel<<<B_*C_, 256>>>(sd, sf);
    gemm2_kernel<<<256, 256, GEMM2_SMEM>>>((float*)d_out);
}